// round 5
// baseline (speedup 1.0000x reference)
#include <cuda_runtime.h>
#include <math.h>
#include <stdint.h>

// ---------------------------------------------------------------------------
// Problem constants
// ---------------------------------------------------------------------------
#define BATCH 4
#define SEQ 4096
#define DIM 1024
#define NHEAD 16
#define HDIM 64
#define M_ROWS (BATCH * SEQ)      // 16384
#define QKV_COLS (3 * DIM)        // 3072
#define NCHUNK 16                 // K2 sequence split
#define CHUNK_ROWS (SEQ / NCHUNK) // 256

// Scratch (device globals; allocation-free contract)
__device__ float g_qkv[(size_t)M_ROWS * QKV_COLS];
__device__ float g_attn[(size_t)M_ROWS * DIM];
__device__ float g_xr[(size_t)M_ROWS * DIM];
__device__ float g_wqkvr[(size_t)DIM * QKV_COLS];
__device__ float g_wprojr[(size_t)DIM * DIM];
__device__ float g_kv[BATCH * NHEAD * HDIM * HDIM];
__device__ float g_ksum[BATCH * NHEAD * HDIM];
__device__ float g_kvp[NCHUNK * BATCH * NHEAD * HDIM * HDIM];
__device__ float g_ksump[NCHUNK * BATCH * NHEAD * HDIM];

// ---------------------------------------------------------------------------
// Smem geometry (pitches picked for conflict-free fragment LDS)
// ---------------------------------------------------------------------------
#define APITCH 36                       // floats per A row
#define BPITCH 136                      // floats per B row
#define A_ST_FLOATS (128 * APITCH)      // 4608
#define B_ST_FLOATS (32 * BPITCH)       // 4352
#define STAGE_FLOATS (A_ST_FLOATS + B_ST_FLOATS)   // 8960
#define GSTAGES 3
#define SMEM_BYTES (GSTAGES * STAGE_FLOATS * 4)    // 107520

__device__ __forceinline__ uint32_t smem_u32(const void* p) {
    uint32_t a;
    asm("{ .reg .u64 t; cvta.to.shared.u64 t, %1; cvt.u32.u64 %0, t; }"
        : "=r"(a) : "l"(p));
    return a;
}
__device__ __forceinline__ void cp16(uint32_t dst, const void* src) {
    asm volatile("cp.async.cg.shared.global [%0], [%1], 16;" :: "r"(dst), "l"(src));
}
__device__ __forceinline__ float f2tf32(float f) {
    float r;
    asm("cvt.rna.tf32.f32 %0, %1;" : "=f"(r) : "f"(f));
    return r;
}
__device__ __forceinline__ void mma_m16n8k8(float* c, const uint32_t* a, const uint32_t* b) {
    asm volatile(
        "mma.sync.aligned.m16n8k8.row.col.f32.tf32.tf32.f32 "
        "{%0,%1,%2,%3}, {%4,%5,%6,%7}, {%8,%9}, {%0,%1,%2,%3};"
        : "+f"(c[0]), "+f"(c[1]), "+f"(c[2]), "+f"(c[3])
        : "r"(a[0]), "r"(a[1]), "r"(a[2]), "r"(a[3]), "r"(b[0]), "r"(b[1]));
}

// ---------------------------------------------------------------------------
// Tensor-core GEMM: C[M,N] = A[M,1024] @ B[1024,N], inputs pre-rounded tf32.
// CTA 128x128, 8 warps (warp tile 32x64), K-tile 32, 3-stage cp.async,
// one __syncthreads per k-tile.
// MODE 1: elu(v)+1 on global cols < 2048 ; MODE 2: v += bias[col]
// ---------------------------------------------------------------------------
template <int MODE>
__global__ __launch_bounds__(256, 2) void gemm_mma(
    const float* __restrict__ A, const float* __restrict__ B,
    float* __restrict__ C, int N, const float* __restrict__ bias)
{
    extern __shared__ float sm[];

    const int tid = threadIdx.x;
    const int bm = blockIdx.y * 128;
    const int bn = blockIdx.x * 128;
    const int lane = tid & 31, wid = tid >> 5;
    const int g = lane >> 2, tg = lane & 3;
    const int mw = (wid >> 1) * 32;       // warp M offset
    const int nw = (wid & 1) * 64;        // warp N offset

    float acc[2][8][4];
#pragma unroll
    for (int mi = 0; mi < 2; mi++)
#pragma unroll
        for (int ni = 0; ni < 8; ni++)
#pragma unroll
            for (int j = 0; j < 4; j++) acc[mi][ni][j] = 0.f;

    const uint32_t s0 = smem_u32(sm);

    // ---- tile loader (cp.async, 16B chunks; 256 threads -> 4 iters each) ----
    auto load_tile = [&](int kt, int s) {
        const uint32_t sA = s0 + s * STAGE_FLOATS * 4;
        const uint32_t sB = sA + A_ST_FLOATS * 4;
#pragma unroll
        for (int i = 0; i < 4; i++) {               // A: 128 rows x 8 chunks
            int c = tid + i * 256;
            int row = c >> 3;
            int off = (c & 7) * 4;
            const float* gp = A + (size_t)(bm + row) * DIM + kt * 32 + off;
            cp16(sA + (row * APITCH + off) * 4, gp);
        }
#pragma unroll
        for (int i = 0; i < 4; i++) {               // B: 32 rows x 32 chunks
            int c = tid + i * 256;
            int row = c >> 5;
            int col = (c & 31) * 4;
            const float* gp = B + (size_t)(kt * 32 + row) * N + bn + col;
            cp16(sB + (row * BPITCH + col) * 4, gp);
        }
        asm volatile("cp.async.commit_group;" ::: "memory");
    };

    const int NT = DIM / 32;              // 32 k-tiles
    load_tile(0, 0);
    load_tile(1, 1);

    int s = 0;
    for (int kt = 0; kt < NT; ++kt) {
        if (kt < NT - 1) {
            asm volatile("cp.async.wait_group 1;" ::: "memory");
        } else {
            asm volatile("cp.async.wait_group 0;" ::: "memory");
        }
        __syncthreads();   // (a) tile kt visible to all warps
                           // (b) all warps done reading stage (kt+2)%3 (used at kt-1)
        if (kt + 2 < NT) {
            int s2 = s + 2; if (s2 >= GSTAGES) s2 -= GSTAGES;
            load_tile(kt + 2, s2);
        }

        const uint32_t* pa = reinterpret_cast<const uint32_t*>(sm + s * STAGE_FLOATS);
        const uint32_t* pb = reinterpret_cast<const uint32_t*>(sm + s * STAGE_FLOATS + A_ST_FLOATS);

#pragma unroll
        for (int ks = 0; ks < 4; ks++) {
            const int k0 = ks * 8;
            uint32_t af[2][4];
#pragma unroll
            for (int mi = 0; mi < 2; mi++) {
                const int r0 = mw + mi * 16;
                af[mi][0] = pa[(r0 + g) * APITCH + k0 + tg];
                af[mi][1] = pa[(r0 + g + 8) * APITCH + k0 + tg];
                af[mi][2] = pa[(r0 + g) * APITCH + k0 + tg + 4];
                af[mi][3] = pa[(r0 + g + 8) * APITCH + k0 + tg + 4];
            }
            uint32_t bf[8][2];
#pragma unroll
            for (int ni = 0; ni < 8; ni++) {
                bf[ni][0] = pb[(k0 + tg) * BPITCH + nw + ni * 8 + g];
                bf[ni][1] = pb[(k0 + tg + 4) * BPITCH + nw + ni * 8 + g];
            }
#pragma unroll
            for (int mi = 0; mi < 2; mi++)
#pragma unroll
                for (int ni = 0; ni < 8; ni++)
                    mma_m16n8k8(acc[mi][ni], af[mi], bf[ni]);
        }
        if (++s >= GSTAGES) s = 0;
    }

    // ---- epilogue: direct global stores ----
#pragma unroll
    for (int mi = 0; mi < 2; mi++) {
#pragma unroll
        for (int ni = 0; ni < 8; ni++) {
            const int row0 = bm + mw + mi * 16 + g;
            const int col = bn + nw + ni * 8 + 2 * tg;
            float v0 = acc[mi][ni][0], v1 = acc[mi][ni][1];
            float v2 = acc[mi][ni][2], v3 = acc[mi][ni][3];
            if (MODE == 1 && col < 2048) {          // elu(x)+1 on q,k columns
                v0 = (v0 > 0.f) ? (v0 + 1.f) : expf(v0);
                v1 = (v1 > 0.f) ? (v1 + 1.f) : expf(v1);
                v2 = (v2 > 0.f) ? (v2 + 1.f) : expf(v2);
                v3 = (v3 > 0.f) ? (v3 + 1.f) : expf(v3);
            }
            if (MODE == 2) {
                float b0 = __ldg(&bias[col]), b1 = __ldg(&bias[col + 1]);
                v0 += b0; v1 += b1; v2 += b0; v3 += b1;
            }
            *reinterpret_cast<float2*>(&C[(size_t)row0 * N + col]) = make_float2(v0, v1);
            *reinterpret_cast<float2*>(&C[(size_t)(row0 + 8) * N + col]) = make_float2(v2, v3);
        }
    }
}

// ---------------------------------------------------------------------------
// Streaming tf32 rounding pass
// ---------------------------------------------------------------------------
__global__ void round_tf32_kernel(const float4* __restrict__ in,
                                  float4* __restrict__ outp, int n4)
{
    int i = blockIdx.x * blockDim.x + threadIdx.x;
    int stride = gridDim.x * blockDim.x;
    for (; i < n4; i += stride) {
        float4 v = in[i];
        v.x = f2tf32(v.x); v.y = f2tf32(v.y); v.z = f2tf32(v.z); v.w = f2tf32(v.w);
        outp[i] = v;
    }
}

// ---------------------------------------------------------------------------
// K2a: partial kv/ksum per (chunk, b, h) over CHUNK_ROWS sequence positions
// ---------------------------------------------------------------------------
__global__ __launch_bounds__(256) void kv_partial_kernel()
{
    const int bh = blockIdx.x;              // 0..63
    const int chunk = blockIdx.y;           // 0..NCHUNK-1
    const int b = bh >> 4, h = bh & 15;

    __shared__ float Ks[32][64];
    __shared__ float Vs[32][64];

    const int tid = threadIdx.x;
    const int tx = tid & 15, ty = tid >> 4;
    const int lr = tid >> 3;
    const int lc = (tid & 7) * 8;

    const float* base = g_qkv + (size_t)b * SEQ * QKV_COLS;
    const int k_col = DIM + h * HDIM;
    const int v_col = 2 * DIM + h * HDIM;

    float acc[4][4];
#pragma unroll
    for (int i = 0; i < 4; i++)
#pragma unroll
        for (int j = 0; j < 4; j++) acc[i][j] = 0.f;
    float ksum = 0.f;

    const int nbeg = chunk * CHUNK_ROWS;
    for (int n0 = nbeg; n0 < nbeg + CHUNK_ROWS; n0 += 32) {
        const float* kp = base + (size_t)(n0 + lr) * QKV_COLS + k_col + lc;
        const float* vp = base + (size_t)(n0 + lr) * QKV_COLS + v_col + lc;
        *reinterpret_cast<float4*>(&Ks[lr][lc])     = *reinterpret_cast<const float4*>(kp);
        *reinterpret_cast<float4*>(&Ks[lr][lc + 4]) = *reinterpret_cast<const float4*>(kp + 4);
        *reinterpret_cast<float4*>(&Vs[lr][lc])     = *reinterpret_cast<const float4*>(vp);
        *reinterpret_cast<float4*>(&Vs[lr][lc + 4]) = *reinterpret_cast<const float4*>(vp + 4);
        __syncthreads();

#pragma unroll 8
        for (int kk = 0; kk < 32; kk++) {
            float rk[4], rv[4];
            *reinterpret_cast<float4*>(rk) = *reinterpret_cast<float4*>(&Ks[kk][ty * 4]);
            *reinterpret_cast<float4*>(rv) = *reinterpret_cast<float4*>(&Vs[kk][tx * 4]);
#pragma unroll
            for (int i = 0; i < 4; i++)
#pragma unroll
                for (int j = 0; j < 4; j++)
                    acc[i][j] = fmaf(rk[i], rv[j], acc[i][j]);
        }
        if (tid < 64) {
#pragma unroll
            for (int kk = 0; kk < 32; kk++) ksum += Ks[kk][tid];
        }
        __syncthreads();
    }

    float* kvout = g_kvp + ((size_t)chunk * 64 + bh) * HDIM * HDIM;
#pragma unroll
    for (int i = 0; i < 4; i++) {
        float4 v = make_float4(acc[i][0], acc[i][1], acc[i][2], acc[i][3]);
        *reinterpret_cast<float4*>(&kvout[(ty * 4 + i) * HDIM + tx * 4]) = v;
    }
    if (tid < 64) g_ksump[(chunk * 64 + bh) * HDIM + tid] = ksum;
}

// K2b: deterministic reduction over chunks
__global__ __launch_bounds__(256) void kv_reduce_kernel()
{
    const int bh = blockIdx.x;
    const int tid = threadIdx.x;
    for (int e = tid; e < HDIM * HDIM; e += 256) {
        float s = 0.f;
#pragma unroll
        for (int c = 0; c < NCHUNK; c++)
            s += g_kvp[((size_t)c * 64 + bh) * HDIM * HDIM + e];
        g_kv[(size_t)bh * HDIM * HDIM + e] = s;
    }
    if (tid < HDIM) {
        float s = 0.f;
#pragma unroll
        for (int c = 0; c < NCHUNK; c++)
            s += g_ksump[(c * 64 + bh) * HDIM + tid];
        g_ksum[bh * HDIM + tid] = s;
    }
}

// ---------------------------------------------------------------------------
// K3: out = (q @ kv) * z ; z = 1/(q . ksum + 1e-6); store tf32-rounded
// ---------------------------------------------------------------------------
__global__ __launch_bounds__(256) void attn_out_kernel()
{
    const int bh = blockIdx.y;
    const int b = bh >> 4, h = bh & 15;
    const int n0 = blockIdx.x * 64;

    __shared__ float Qs[64][65];
    __shared__ float KVs[64 * 64];
    __shared__ float ksums[64];
    __shared__ float zsh[64];

    const int tid = threadIdx.x;

    const float* kvsrc = g_kv + (size_t)bh * HDIM * HDIM;
    for (int i = tid; i < (HDIM * HDIM) / 4; i += 256)
        reinterpret_cast<float4*>(KVs)[i] = reinterpret_cast<const float4*>(kvsrc)[i];
    if (tid < 64) ksums[tid] = g_ksum[bh * HDIM + tid];

    {
        const int qr = tid >> 2;
        const int qc = (tid & 3) * 16;
        const float* qbase = g_qkv + (size_t)(b * SEQ + n0 + qr) * QKV_COLS + h * HDIM + qc;
#pragma unroll
        for (int c = 0; c < 16; c += 4) {
            float4 v = *reinterpret_cast<const float4*>(qbase + c);
            Qs[qr][qc + c + 0] = v.x;
            Qs[qr][qc + c + 1] = v.y;
            Qs[qr][qc + c + 2] = v.z;
            Qs[qr][qc + c + 3] = v.w;
        }
    }
    __syncthreads();

    if (tid < 64) {
        float dot = 0.f;
#pragma unroll 8
        for (int d = 0; d < 64; d++) dot = fmaf(Qs[tid][d], ksums[d], dot);
        zsh[tid] = 1.f / (dot + 1e-6f);
    }
    __syncthreads();

    const int tx = tid & 15, ty = tid >> 4;
    const int r0 = ty * 4;
    const int e0 = tx * 4;

    float acc[4][4];
#pragma unroll
    for (int i = 0; i < 4; i++)
#pragma unroll
        for (int j = 0; j < 4; j++) acc[i][j] = 0.f;

#pragma unroll 4
    for (int d = 0; d < 64; d++) {
        float rb[4];
        *reinterpret_cast<float4*>(rb) = *reinterpret_cast<float4*>(&KVs[d * 64 + e0]);
        float ra0 = Qs[r0 + 0][d];
        float ra1 = Qs[r0 + 1][d];
        float ra2 = Qs[r0 + 2][d];
        float ra3 = Qs[r0 + 3][d];
#pragma unroll
        for (int j = 0; j < 4; j++) {
            acc[0][j] = fmaf(ra0, rb[j], acc[0][j]);
            acc[1][j] = fmaf(ra1, rb[j], acc[1][j]);
            acc[2][j] = fmaf(ra2, rb[j], acc[2][j]);
            acc[3][j] = fmaf(ra3, rb[j], acc[3][j]);
        }
    }

#pragma unroll
    for (int i = 0; i < 4; i++) {
        float z = zsh[r0 + i];
        // tf32-rounded: this array is the A operand of the K4 tensor GEMM
        float4 v = make_float4(f2tf32(acc[i][0] * z), f2tf32(acc[i][1] * z),
                               f2tf32(acc[i][2] * z), f2tf32(acc[i][3] * z));
        size_t row = (size_t)(b * SEQ + n0 + r0 + i);
        *reinterpret_cast<float4*>(&g_attn[row * DIM + h * HDIM + e0]) = v;
    }
}

// ---------------------------------------------------------------------------
extern "C" void kernel_launch(void* const* d_in, const int* in_sizes, int n_in,
                              void* d_out, int out_size)
{
    const float* x      = (const float*)d_in[0];  // [4,4096,1024]
    const float* W_qkv  = (const float*)d_in[1];  // [1024,3072]
    const float* W_proj = (const float*)d_in[2];  // [1024,1024]
    const float* b_proj = (const float*)d_in[3];  // [1024]
    float* out = (float*)d_out;

    float *qkv_p, *attn_p, *xr_p, *wqkvr_p, *wprojr_p;
    cudaGetSymbolAddress((void**)&qkv_p, g_qkv);
    cudaGetSymbolAddress((void**)&attn_p, g_attn);
    cudaGetSymbolAddress((void**)&xr_p, g_xr);
    cudaGetSymbolAddress((void**)&wqkvr_p, g_wqkvr);
    cudaGetSymbolAddress((void**)&wprojr_p, g_wprojr);

    cudaFuncSetAttribute(gemm_mma<1>, cudaFuncAttributeMaxDynamicSharedMemorySize, SMEM_BYTES);
    cudaFuncSetAttribute(gemm_mma<2>, cudaFuncAttributeMaxDynamicSharedMemorySize, SMEM_BYTES);

    // tf32 pre-rounding passes (removes cvt from GEMM inner loops)
    round_tf32_kernel<<<2048, 256>>>((const float4*)x, (float4*)xr_p,
                                     (int)((size_t)M_ROWS * DIM / 4));
    round_tf32_kernel<<<1024, 256>>>((const float4*)W_qkv, (float4*)wqkvr_p,
                                     (int)((size_t)DIM * QKV_COLS / 4));
    round_tf32_kernel<<<512, 256>>>((const float4*)W_proj, (float4*)wprojr_p,
                                    (int)((size_t)DIM * DIM / 4));

    // K1: qkv = x @ W_qkv, elu+1 fused on q/k columns
    gemm_mma<1><<<dim3(QKV_COLS / 128, M_ROWS / 128), 256, SMEM_BYTES>>>(
        xr_p, wqkvr_p, qkv_p, QKV_COLS, nullptr);

    // K2: kv state + ksum (chunked + deterministic reduce)
    kv_partial_kernel<<<dim3(BATCH * NHEAD, NCHUNK), 256>>>();
    kv_reduce_kernel<<<BATCH * NHEAD, 256>>>();

    // K3: normalized readout (stores tf32-rounded)
    attn_out_kernel<<<dim3(SEQ / 64, BATCH * NHEAD), 256>>>();

    // K4: out = attn @ W_proj + b_proj
    gemm_mma<2><<<dim3(DIM / 128, M_ROWS / 128), 256, SMEM_BYTES>>>(
        attn_p, wprojr_p, out, DIM, b_proj);
}

// round 6
// speedup vs baseline: 1.8235x; 1.8235x over previous
#include <cuda_runtime.h>
#include <cuda_fp16.h>
#include <math.h>
#include <stdint.h>

// ---------------------------------------------------------------------------
// Problem constants
// ---------------------------------------------------------------------------
#define BATCH 4
#define SEQ 4096
#define DIM 1024
#define NHEAD 16
#define HDIM 64
#define M_ROWS (BATCH * SEQ)      // 16384
#define QKV_COLS (3 * DIM)        // 3072
#define NCHUNK 16
#define CHUNK_ROWS (SEQ / NCHUNK)

// Scratch (device globals; allocation-free contract)
__device__ float  g_qkv[(size_t)M_ROWS * QKV_COLS];
__device__ __half g_xh[(size_t)M_ROWS * DIM];
__device__ __half g_attnh[(size_t)M_ROWS * DIM];
__device__ __half g_wqkvh[(size_t)DIM * QKV_COLS];
__device__ __half g_wprojh[(size_t)DIM * DIM];
__device__ float  g_kv[BATCH * NHEAD * HDIM * HDIM];
__device__ float  g_ksum[BATCH * NHEAD * HDIM];
__device__ float  g_kvp[NCHUNK * BATCH * NHEAD * HDIM * HDIM];
__device__ float  g_ksump[NCHUNK * BATCH * NHEAD * HDIM];

// ---------------------------------------------------------------------------
// GEMM geometry: CTA 128(M) x 128(N), K-tile 64 halves, 3-stage cp.async.
// A smem: [128 rows][64 halves] = 128B/row, SW128 swizzle.
// B smem: [64 k-rows][128 n-halves] = 256B/row, low-3-bit chunk swizzle.
// ---------------------------------------------------------------------------
#define KT 64
#define NT (DIM / KT)                   // 16 k-tiles
#define A_STAGE_BYTES (128 * 128)       // 16384
#define B_STAGE_BYTES (64 * 256)        // 16384
#define STAGE_BYTES (A_STAGE_BYTES + B_STAGE_BYTES)
#define GSTAGES 3
#define SMEM_BYTES (GSTAGES * STAGE_BYTES)   // 98304

__device__ __forceinline__ uint32_t smem_u32(const void* p) {
    uint32_t a;
    asm("{ .reg .u64 t; cvta.to.shared.u64 t, %1; cvt.u32.u64 %0, t; }"
        : "=r"(a) : "l"(p));
    return a;
}
__device__ __forceinline__ void cp16(uint32_t dst, const void* src) {
    asm volatile("cp.async.cg.shared.global [%0], [%1], 16;" :: "r"(dst), "l"(src));
}
__device__ __forceinline__ void ldsm4(uint32_t& r0, uint32_t& r1, uint32_t& r2,
                                      uint32_t& r3, uint32_t a) {
    asm volatile("ldmatrix.sync.aligned.m8n8.x4.shared.b16 {%0,%1,%2,%3}, [%4];"
                 : "=r"(r0), "=r"(r1), "=r"(r2), "=r"(r3) : "r"(a));
}
__device__ __forceinline__ void ldsm4t(uint32_t& r0, uint32_t& r1, uint32_t& r2,
                                       uint32_t& r3, uint32_t a) {
    asm volatile("ldmatrix.sync.aligned.m8n8.x4.trans.shared.b16 {%0,%1,%2,%3}, [%4];"
                 : "=r"(r0), "=r"(r1), "=r"(r2), "=r"(r3) : "r"(a));
}
__device__ __forceinline__ void mma16816(float* c, const uint32_t* a, const uint32_t* b) {
    asm volatile(
        "mma.sync.aligned.m16n8k16.row.col.f32.f16.f16.f32 "
        "{%0,%1,%2,%3}, {%4,%5,%6,%7}, {%8,%9}, {%0,%1,%2,%3};"
        : "+f"(c[0]), "+f"(c[1]), "+f"(c[2]), "+f"(c[3])
        : "r"(a[0]), "r"(a[1]), "r"(a[2]), "r"(a[3]), "r"(b[0]), "r"(b[1]));
}

// ---------------------------------------------------------------------------
// fp16 tensor GEMM: C[M,N] = Ah[M,1024] @ Bh[1024,N] (Bh row-major [K][N]).
// 8 warps, warp tile 32x64. MODE 1: elu+1 on cols<2048; MODE 2: += bias.
// ---------------------------------------------------------------------------
template <int MODE>
__global__ __launch_bounds__(256, 2) void gemm_h(
    const __half* __restrict__ Ah, const __half* __restrict__ Bh,
    float* __restrict__ C, int N, const float* __restrict__ bias)
{
    extern __shared__ char sm[];

    const int tid = threadIdx.x;
    const int bm = blockIdx.y * 128;
    const int bn = blockIdx.x * 128;
    const int lane = tid & 31, wid = tid >> 5;
    const int g = lane >> 2, tg = lane & 3;
    const int mw = (wid >> 1) * 32;       // warp M offset
    const int nw = (wid & 1) * 64;        // warp N offset
    const int l7 = lane & 7;
    const int grp = lane >> 3;            // 0..3 (ldmatrix address group)

    float acc[2][8][4];
#pragma unroll
    for (int mi = 0; mi < 2; mi++)
#pragma unroll
        for (int ni = 0; ni < 8; ni++)
#pragma unroll
            for (int j = 0; j < 4; j++) acc[mi][ni][j] = 0.f;

    const uint32_t s0 = smem_u32(sm);

    // ---- tile loader: A 1024 chunks + B 1024 chunks of 16B; 8/thread ----
    auto load_tile = [&](int kt, int s) {
        const uint32_t sA = s0 + s * STAGE_BYTES;
        const uint32_t sB = sA + A_STAGE_BYTES;
#pragma unroll
        for (int i = 0; i < 4; i++) {               // A: 128 rows x 8 chunks
            int id = tid + i * 256;
            int row = id >> 3, c = id & 7;
            const __half* gp = Ah + (size_t)(bm + row) * DIM + kt * KT + c * 8;
            cp16(sA + row * 128 + ((c ^ (row & 7)) << 4), gp);
        }
#pragma unroll
        for (int i = 0; i < 4; i++) {               // B: 64 k-rows x 16 chunks
            int id = tid + i * 256;
            int row = id >> 4, c = id & 15;
            const __half* gp = Bh + (size_t)(kt * KT + row) * N + bn + c * 8;
            cp16(sB + row * 256 + ((c ^ (row & 7)) << 4), gp);
        }
        asm volatile("cp.async.commit_group;" ::: "memory");
    };

    load_tile(0, 0);
    load_tile(1, 1);

    int s = 0;
    for (int kt = 0; kt < NT; ++kt) {
        if (kt < NT - 1) {
            asm volatile("cp.async.wait_group 1;" ::: "memory");
        } else {
            asm volatile("cp.async.wait_group 0;" ::: "memory");
        }
        __syncthreads();
        if (kt + 2 < NT) {
            int s2 = s + 2; if (s2 >= GSTAGES) s2 -= GSTAGES;
            load_tile(kt + 2, s2);
        }

        const uint32_t sA = s0 + s * STAGE_BYTES;
        const uint32_t sB = sA + A_STAGE_BYTES;

#pragma unroll
        for (int ks = 0; ks < 4; ks++) {            // k16 steps within tile
            const int c0 = ks * 2;                  // 16B-chunk index of k0

            // A fragments (row-major, non-trans):
            // grp0: rows r0+l7,   chunk c0   ; grp1: rows r0+8+l7, chunk c0
            // grp2: rows r0+l7,   chunk c0+1 ; grp3: rows r0+8+l7, chunk c0+1
            uint32_t af[2][4];
#pragma unroll
            for (int mi = 0; mi < 2; mi++) {
                int row = mw + mi * 16 + l7 + (grp & 1) * 8;
                int c = c0 + (grp >> 1);
                uint32_t a = sA + row * 128 + ((c ^ (row & 7)) << 4);
                ldsm4(af[mi][0], af[mi][1], af[mi][2], af[mi][3], a);
            }

            // B fragments ([K][N] storage, trans):
            // grp0: k-rows k0+l7, n-chunk cn ; grp1: k-rows k0+8+l7, n-chunk cn
            // grp2: k-rows k0+l7, cn+1       ; grp3: k-rows k0+8+l7, cn+1
            uint32_t bf[8][2];
#pragma unroll
            for (int nj = 0; nj < 4; nj++) {
                int row = ks * 16 + l7 + (grp & 1) * 8;
                int c = (nw >> 3) + nj * 2 + (grp >> 1);
                uint32_t a = sB + row * 256 + ((c ^ (row & 7)) << 4);
                ldsm4t(bf[2 * nj][0], bf[2 * nj][1], bf[2 * nj + 1][0], bf[2 * nj + 1][1], a);
            }

#pragma unroll
            for (int mi = 0; mi < 2; mi++)
#pragma unroll
                for (int ni = 0; ni < 8; ni++)
                    mma16816(acc[mi][ni], af[mi], bf[ni]);
        }
        if (++s >= GSTAGES) s = 0;
    }

    // ---- epilogue ----
#pragma unroll
    for (int mi = 0; mi < 2; mi++) {
#pragma unroll
        for (int ni = 0; ni < 8; ni++) {
            const int row0 = bm + mw + mi * 16 + g;
            const int col = bn + nw + ni * 8 + 2 * tg;
            float v0 = acc[mi][ni][0], v1 = acc[mi][ni][1];
            float v2 = acc[mi][ni][2], v3 = acc[mi][ni][3];
            if (MODE == 1 && col < 2048) {          // elu(x)+1 on q,k columns
                v0 = (v0 > 0.f) ? (v0 + 1.f) : expf(v0);
                v1 = (v1 > 0.f) ? (v1 + 1.f) : expf(v1);
                v2 = (v2 > 0.f) ? (v2 + 1.f) : expf(v2);
                v3 = (v3 > 0.f) ? (v3 + 1.f) : expf(v3);
            }
            if (MODE == 2) {
                float b0 = __ldg(&bias[col]), b1 = __ldg(&bias[col + 1]);
                v0 += b0; v1 += b1; v2 += b0; v3 += b1;
            }
            *reinterpret_cast<float2*>(&C[(size_t)row0 * N + col]) = make_float2(v0, v1);
            *reinterpret_cast<float2*>(&C[(size_t)(row0 + 8) * N + col]) = make_float2(v2, v3);
        }
    }
}

// ---------------------------------------------------------------------------
// fp32 -> fp16 elementwise convert (grid-stride)
// ---------------------------------------------------------------------------
__global__ void f32_to_f16_kernel(const float4* __restrict__ in,
                                  uint2* __restrict__ outp, int n4)
{
    int i = blockIdx.x * blockDim.x + threadIdx.x;
    int stride = gridDim.x * blockDim.x;
    for (; i < n4; i += stride) {
        float4 v = in[i];
        __half2 a = __floats2half2_rn(v.x, v.y);
        __half2 b = __floats2half2_rn(v.z, v.w);
        uint2 o;
        o.x = *reinterpret_cast<uint32_t*>(&a);
        o.y = *reinterpret_cast<uint32_t*>(&b);
        outp[i] = o;
    }
}

// ---------------------------------------------------------------------------
// K2a: partial kv/ksum per (chunk, b, h)
// ---------------------------------------------------------------------------
__global__ __launch_bounds__(256) void kv_partial_kernel()
{
    const int bh = blockIdx.x;
    const int chunk = blockIdx.y;
    const int b = bh >> 4, h = bh & 15;

    __shared__ float Ks[32][64];
    __shared__ float Vs[32][64];

    const int tid = threadIdx.x;
    const int tx = tid & 15, ty = tid >> 4;
    const int lr = tid >> 3;
    const int lc = (tid & 7) * 8;

    const float* base = g_qkv + (size_t)b * SEQ * QKV_COLS;
    const int k_col = DIM + h * HDIM;
    const int v_col = 2 * DIM + h * HDIM;

    float acc[4][4];
#pragma unroll
    for (int i = 0; i < 4; i++)
#pragma unroll
        for (int j = 0; j < 4; j++) acc[i][j] = 0.f;
    float ksum = 0.f;

    const int nbeg = chunk * CHUNK_ROWS;
    for (int n0 = nbeg; n0 < nbeg + CHUNK_ROWS; n0 += 32) {
        const float* kp = base + (size_t)(n0 + lr) * QKV_COLS + k_col + lc;
        const float* vp = base + (size_t)(n0 + lr) * QKV_COLS + v_col + lc;
        *reinterpret_cast<float4*>(&Ks[lr][lc])     = *reinterpret_cast<const float4*>(kp);
        *reinterpret_cast<float4*>(&Ks[lr][lc + 4]) = *reinterpret_cast<const float4*>(kp + 4);
        *reinterpret_cast<float4*>(&Vs[lr][lc])     = *reinterpret_cast<const float4*>(vp);
        *reinterpret_cast<float4*>(&Vs[lr][lc + 4]) = *reinterpret_cast<const float4*>(vp + 4);
        __syncthreads();

#pragma unroll 8
        for (int kk = 0; kk < 32; kk++) {
            float rk[4], rv[4];
            *reinterpret_cast<float4*>(rk) = *reinterpret_cast<float4*>(&Ks[kk][ty * 4]);
            *reinterpret_cast<float4*>(rv) = *reinterpret_cast<float4*>(&Vs[kk][tx * 4]);
#pragma unroll
            for (int i = 0; i < 4; i++)
#pragma unroll
                for (int j = 0; j < 4; j++)
                    acc[i][j] = fmaf(rk[i], rv[j], acc[i][j]);
        }
        if (tid < 64) {
#pragma unroll
            for (int kk = 0; kk < 32; kk++) ksum += Ks[kk][tid];
        }
        __syncthreads();
    }

    float* kvout = g_kvp + ((size_t)chunk * 64 + bh) * HDIM * HDIM;
#pragma unroll
    for (int i = 0; i < 4; i++) {
        float4 v = make_float4(acc[i][0], acc[i][1], acc[i][2], acc[i][3]);
        *reinterpret_cast<float4*>(&kvout[(ty * 4 + i) * HDIM + tx * 4]) = v;
    }
    if (tid < 64) g_ksump[(chunk * 64 + bh) * HDIM + tid] = ksum;
}

// K2b: deterministic reduction over chunks
__global__ __launch_bounds__(256) void kv_reduce_kernel()
{
    const int bh = blockIdx.x;
    const int tid = threadIdx.x;
    for (int e = tid; e < HDIM * HDIM; e += 256) {
        float s = 0.f;
#pragma unroll
        for (int c = 0; c < NCHUNK; c++)
            s += g_kvp[((size_t)c * 64 + bh) * HDIM * HDIM + e];
        g_kv[(size_t)bh * HDIM * HDIM + e] = s;
    }
    if (tid < HDIM) {
        float s = 0.f;
#pragma unroll
        for (int c = 0; c < NCHUNK; c++)
            s += g_ksump[(c * 64 + bh) * HDIM + tid];
        g_ksum[bh * HDIM + tid] = s;
    }
}

// ---------------------------------------------------------------------------
// K3: out = (q @ kv) * z ; z = 1/(q . ksum + 1e-6); writes fp16 (K4's A)
// ---------------------------------------------------------------------------
__global__ __launch_bounds__(256) void attn_out_kernel()
{
    const int bh = blockIdx.y;
    const int b = bh >> 4, h = bh & 15;
    const int n0 = blockIdx.x * 64;

    __shared__ float Qs[64][65];
    __shared__ float KVs[64 * 64];
    __shared__ float ksums[64];
    __shared__ float zsh[64];

    const int tid = threadIdx.x;

    const float* kvsrc = g_kv + (size_t)bh * HDIM * HDIM;
    for (int i = tid; i < (HDIM * HDIM) / 4; i += 256)
        reinterpret_cast<float4*>(KVs)[i] = reinterpret_cast<const float4*>(kvsrc)[i];
    if (tid < 64) ksums[tid] = g_ksum[bh * HDIM + tid];

    {
        const int qr = tid >> 2;
        const int qc = (tid & 3) * 16;
        const float* qbase = g_qkv + (size_t)(b * SEQ + n0 + qr) * QKV_COLS + h * HDIM + qc;
#pragma unroll
        for (int c = 0; c < 16; c += 4) {
            float4 v = *reinterpret_cast<const float4*>(qbase + c);
            Qs[qr][qc + c + 0] = v.x;
            Qs[qr][qc + c + 1] = v.y;
            Qs[qr][qc + c + 2] = v.z;
            Qs[qr][qc + c + 3] = v.w;
        }
    }
    __syncthreads();

    if (tid < 64) {
        float dot = 0.f;
#pragma unroll 8
        for (int d = 0; d < 64; d++) dot = fmaf(Qs[tid][d], ksums[d], dot);
        zsh[tid] = 1.f / (dot + 1e-6f);
    }
    __syncthreads();

    const int tx = tid & 15, ty = tid >> 4;
    const int r0 = ty * 4;
    const int e0 = tx * 4;

    float acc[4][4];
#pragma unroll
    for (int i = 0; i < 4; i++)
#pragma unroll
        for (int j = 0; j < 4; j++) acc[i][j] = 0.f;

#pragma unroll 4
    for (int d = 0; d < 64; d++) {
        float rb[4];
        *reinterpret_cast<float4*>(rb) = *reinterpret_cast<float4*>(&KVs[d * 64 + e0]);
        float ra0 = Qs[r0 + 0][d];
        float ra1 = Qs[r0 + 1][d];
        float ra2 = Qs[r0 + 2][d];
        float ra3 = Qs[r0 + 3][d];
#pragma unroll
        for (int j = 0; j < 4; j++) {
            acc[0][j] = fmaf(ra0, rb[j], acc[0][j]);
            acc[1][j] = fmaf(ra1, rb[j], acc[1][j]);
            acc[2][j] = fmaf(ra2, rb[j], acc[2][j]);
            acc[3][j] = fmaf(ra3, rb[j], acc[3][j]);
        }
    }

#pragma unroll
    for (int i = 0; i < 4; i++) {
        float z = zsh[r0 + i];
        __half2 h01 = __floats2half2_rn(acc[i][0] * z, acc[i][1] * z);
        __half2 h23 = __floats2half2_rn(acc[i][2] * z, acc[i][3] * z);
        uint2 o;
        o.x = *reinterpret_cast<uint32_t*>(&h01);
        o.y = *reinterpret_cast<uint32_t*>(&h23);
        size_t row = (size_t)(b * SEQ + n0 + r0 + i);
        *reinterpret_cast<uint2*>(&g_attnh[row * DIM + h * HDIM + e0]) = o;
    }
}

// ---------------------------------------------------------------------------
extern "C" void kernel_launch(void* const* d_in, const int* in_sizes, int n_in,
                              void* d_out, int out_size)
{
    const float* x      = (const float*)d_in[0];  // [4,4096,1024]
    const float* W_qkv  = (const float*)d_in[1];  // [1024,3072]
    const float* W_proj = (const float*)d_in[2];  // [1024,1024]
    const float* b_proj = (const float*)d_in[3];  // [1024]
    float* out = (float*)d_out;

    float *qkv_p;
    __half *xh_p, *attnh_p, *wqkvh_p, *wprojh_p;
    cudaGetSymbolAddress((void**)&qkv_p, g_qkv);
    cudaGetSymbolAddress((void**)&xh_p, g_xh);
    cudaGetSymbolAddress((void**)&attnh_p, g_attnh);
    cudaGetSymbolAddress((void**)&wqkvh_p, g_wqkvh);
    cudaGetSymbolAddress((void**)&wprojh_p, g_wprojh);

    cudaFuncSetAttribute(gemm_h<1>, cudaFuncAttributeMaxDynamicSharedMemorySize, SMEM_BYTES);
    cudaFuncSetAttribute(gemm_h<2>, cudaFuncAttributeMaxDynamicSharedMemorySize, SMEM_BYTES);

    // fp32 -> fp16 conversion passes
    f32_to_f16_kernel<<<2048, 256>>>((const float4*)x, (uint2*)xh_p,
                                     (int)((size_t)M_ROWS * DIM / 4));
    f32_to_f16_kernel<<<1024, 256>>>((const float4*)W_qkv, (uint2*)wqkvh_p,
                                     (int)((size_t)DIM * QKV_COLS / 4));
    f32_to_f16_kernel<<<512, 256>>>((const float4*)W_proj, (uint2*)wprojh_p,
                                    (int)((size_t)DIM * DIM / 4));

    // K1: qkv = x @ W_qkv, elu+1 fused on q/k columns
    gemm_h<1><<<dim3(QKV_COLS / 128, M_ROWS / 128), 256, SMEM_BYTES>>>(
        xh_p, wqkvh_p, qkv_p, QKV_COLS, nullptr);

    // K2: kv state + ksum (chunked + deterministic reduce)
    kv_partial_kernel<<<dim3(BATCH * NHEAD, NCHUNK), 256>>>();
    kv_reduce_kernel<<<BATCH * NHEAD, 256>>>();

    // K3: normalized readout (writes fp16 A for K4)
    attn_out_kernel<<<dim3(SEQ / 64, BATCH * NHEAD), 256>>>();

    // K4: out = attn @ W_proj + b_proj
    gemm_h<2><<<dim3(DIM / 128, M_ROWS / 128), 256, SMEM_BYTES>>>(
        attnh_p, wprojh_p, out, DIM, b_proj);
}

// round 7
// speedup vs baseline: 1.8941x; 1.0387x over previous
#include <cuda_runtime.h>
#include <cuda_fp16.h>
#include <math.h>
#include <stdint.h>

// ---------------------------------------------------------------------------
// Problem constants
// ---------------------------------------------------------------------------
#define BATCH 4
#define SEQ 4096
#define DIM 1024
#define NHEAD 16
#define HDIM 64
#define M_ROWS (BATCH * SEQ)      // 16384
#define QKV_COLS (3 * DIM)        // 3072
#define NCHUNK 16
#define CHUNK_ROWS (SEQ / NCHUNK)

// Scratch (device globals; allocation-free contract)
__device__ __half g_qkvh[(size_t)M_ROWS * QKV_COLS];   // fp16 qkv intermediate
__device__ __half g_xh[(size_t)M_ROWS * DIM];
__device__ __half g_attnh[(size_t)M_ROWS * DIM];
__device__ __half g_wqkvh[(size_t)DIM * QKV_COLS];
__device__ __half g_wprojh[(size_t)DIM * DIM];
__device__ float  g_kv[BATCH * NHEAD * HDIM * HDIM];
__device__ float  g_ksum[BATCH * NHEAD * HDIM];
__device__ float  g_kvp[NCHUNK * BATCH * NHEAD * HDIM * HDIM];
__device__ float  g_ksump[NCHUNK * BATCH * NHEAD * HDIM];

// ---------------------------------------------------------------------------
// GEMM geometry: CTA 128(M) x 128(N), K-tile 64 halves, 3-stage cp.async.
// ---------------------------------------------------------------------------
#define KT 64
#define NTILES (DIM / KT)               // 16 k-tiles
#define A_STAGE_BYTES (128 * 128)       // 16384
#define B_STAGE_BYTES (64 * 256)        // 16384
#define STAGE_BYTES (A_STAGE_BYTES + B_STAGE_BYTES)
#define GSTAGES 3
#define SMEM_BYTES (GSTAGES * STAGE_BYTES)   // 98304

__device__ __forceinline__ uint32_t smem_u32(const void* p) {
    uint32_t a;
    asm("{ .reg .u64 t; cvta.to.shared.u64 t, %1; cvt.u32.u64 %0, t; }"
        : "=r"(a) : "l"(p));
    return a;
}
__device__ __forceinline__ void cp16(uint32_t dst, const void* src) {
    asm volatile("cp.async.cg.shared.global [%0], [%1], 16;" :: "r"(dst), "l"(src));
}
__device__ __forceinline__ void ldsm4(uint32_t& r0, uint32_t& r1, uint32_t& r2,
                                      uint32_t& r3, uint32_t a) {
    asm volatile("ldmatrix.sync.aligned.m8n8.x4.shared.b16 {%0,%1,%2,%3}, [%4];"
                 : "=r"(r0), "=r"(r1), "=r"(r2), "=r"(r3) : "r"(a));
}
__device__ __forceinline__ void ldsm4t(uint32_t& r0, uint32_t& r1, uint32_t& r2,
                                       uint32_t& r3, uint32_t a) {
    asm volatile("ldmatrix.sync.aligned.m8n8.x4.trans.shared.b16 {%0,%1,%2,%3}, [%4];"
                 : "=r"(r0), "=r"(r1), "=r"(r2), "=r"(r3) : "r"(a));
}
__device__ __forceinline__ void mma16816(float* c, const uint32_t* a, const uint32_t* b) {
    asm volatile(
        "mma.sync.aligned.m16n8k16.row.col.f32.f16.f16.f32 "
        "{%0,%1,%2,%3}, {%4,%5,%6,%7}, {%8,%9}, {%0,%1,%2,%3};"
        : "+f"(c[0]), "+f"(c[1]), "+f"(c[2]), "+f"(c[3])
        : "r"(a[0]), "r"(a[1]), "r"(a[2]), "r"(a[3]), "r"(b[0]), "r"(b[1]));
}

// ---------------------------------------------------------------------------
// fp16 tensor GEMM: C = Ah[M,1024] @ Bh[1024,N]  (Bh row-major [K][N]).
// 8 warps, warp tile 32x64.
// MODE 1: elu+1 on cols<2048, output __half.  MODE 2: +=bias, output float.
// ---------------------------------------------------------------------------
template <int MODE>
__global__ __launch_bounds__(256, 2) void gemm_h(
    const __half* __restrict__ Ah, const __half* __restrict__ Bh,
    void* __restrict__ Cv, int N, const float* __restrict__ bias)
{
    extern __shared__ char sm[];

    const int tid = threadIdx.x;
    const int bm = blockIdx.y * 128;
    const int bn = blockIdx.x * 128;
    const int lane = tid & 31, wid = tid >> 5;
    const int g = lane >> 2, tg = lane & 3;
    const int mw = (wid >> 1) * 32;       // warp M offset
    const int nw = (wid & 1) * 64;        // warp N offset
    const int l7 = lane & 7;
    const int grp = lane >> 3;            // ldmatrix address group

    float acc[2][8][4];
#pragma unroll
    for (int mi = 0; mi < 2; mi++)
#pragma unroll
        for (int ni = 0; ni < 8; ni++)
#pragma unroll
            for (int j = 0; j < 4; j++) acc[mi][ni][j] = 0.f;

    const uint32_t s0 = smem_u32(sm);

    // ---- hoisted loader smem offsets (constant per thread) ----
    uint32_t ldA_s[4], ldB_s[4];
#pragma unroll
    for (int i = 0; i < 4; i++) {
        int id = tid + i * 256;
        int row = id >> 3, c = id & 7;                  // A: 128 rows x 8 chunks
        ldA_s[i] = row * 128 + ((c ^ (row & 7)) << 4);
        int rowb = id >> 4, cb = id & 15;               // B: 64 rows x 16 chunks
        ldB_s[i] = rowb * 256 + ((cb ^ (rowb & 7)) << 4);
    }

    auto load_tile = [&](int kt, int s) {
        const uint32_t sA = s0 + s * STAGE_BYTES;
        const uint32_t sB = sA + A_STAGE_BYTES;
#pragma unroll
        for (int i = 0; i < 4; i++) {
            int id = tid + i * 256;
            int row = id >> 3, c = id & 7;
            cp16(sA + ldA_s[i], Ah + (size_t)(bm + row) * DIM + kt * KT + c * 8);
        }
#pragma unroll
        for (int i = 0; i < 4; i++) {
            int id = tid + i * 256;
            int row = id >> 4, c = id & 15;
            cp16(sB + ldB_s[i], Bh + (size_t)(kt * KT + row) * N + bn + c * 8);
        }
        asm volatile("cp.async.commit_group;" ::: "memory");
    };

    // ---- hoisted fragment addresses ----
    // A: addr(mi, ks) = sA + aBase[mi] ^ (ks << 5)
    uint32_t aBase[2];
#pragma unroll
    for (int mi = 0; mi < 2; mi++) {
        int row = mw + mi * 16 + l7 + (grp & 1) * 8;
        int g2r = (grp >> 1) ^ (row & 7);
        aBase[mi] = row * 128 + (g2r << 4);
    }
    // B: addr(nj, ks) = sB + bBase[nj] + ks * 4096
    uint32_t bBase[4];
#pragma unroll
    for (int nj = 0; nj < 4; nj++) {
        int brow = l7 + (grp & 1) * 8;
        int c = (nw >> 3) + nj * 2 + (grp >> 1);
        bBase[nj] = brow * 256 + ((c ^ l7) << 4);
    }

    load_tile(0, 0);
    load_tile(1, 1);

    int s = 0;
    for (int kt = 0; kt < NTILES; ++kt) {
        if (kt < NTILES - 1) {
            asm volatile("cp.async.wait_group 1;" ::: "memory");
        } else {
            asm volatile("cp.async.wait_group 0;" ::: "memory");
        }
        __syncthreads();
        if (kt + 2 < NTILES) {
            int s2 = s + 2; if (s2 >= GSTAGES) s2 -= GSTAGES;
            load_tile(kt + 2, s2);
        }

        const uint32_t sA = s0 + s * STAGE_BYTES;
        const uint32_t sB = sA + A_STAGE_BYTES;

#pragma unroll
        for (int ks = 0; ks < 4; ks++) {
            uint32_t af[2][4];
#pragma unroll
            for (int mi = 0; mi < 2; mi++)
                ldsm4(af[mi][0], af[mi][1], af[mi][2], af[mi][3],
                      sA + (aBase[mi] ^ (ks << 5)));

            uint32_t bf[8][2];
#pragma unroll
            for (int nj = 0; nj < 4; nj++)
                ldsm4t(bf[2 * nj][0], bf[2 * nj][1], bf[2 * nj + 1][0], bf[2 * nj + 1][1],
                       sB + bBase[nj] + ks * 4096);

#pragma unroll
            for (int mi = 0; mi < 2; mi++)
#pragma unroll
                for (int ni = 0; ni < 8; ni++)
                    mma16816(acc[mi][ni], af[mi], bf[ni]);
        }
        if (++s >= GSTAGES) s = 0;
    }

    // ---- epilogue ----
#pragma unroll
    for (int mi = 0; mi < 2; mi++) {
#pragma unroll
        for (int ni = 0; ni < 8; ni++) {
            const int row0 = bm + mw + mi * 16 + g;
            const int col = bn + nw + ni * 8 + 2 * tg;
            float v0 = acc[mi][ni][0], v1 = acc[mi][ni][1];
            float v2 = acc[mi][ni][2], v3 = acc[mi][ni][3];
            if (MODE == 1) {
                if (col < 2048) {                       // elu(x)+1 on q,k columns
                    v0 = (v0 > 0.f) ? (v0 + 1.f) : expf(v0);
                    v1 = (v1 > 0.f) ? (v1 + 1.f) : expf(v1);
                    v2 = (v2 > 0.f) ? (v2 + 1.f) : expf(v2);
                    v3 = (v3 > 0.f) ? (v3 + 1.f) : expf(v3);
                }
                __half* Ch = (__half*)Cv;
                *reinterpret_cast<__half2*>(&Ch[(size_t)row0 * N + col]) =
                    __floats2half2_rn(v0, v1);
                *reinterpret_cast<__half2*>(&Ch[(size_t)(row0 + 8) * N + col]) =
                    __floats2half2_rn(v2, v3);
            } else {
                float b0 = __ldg(&bias[col]), b1 = __ldg(&bias[col + 1]);
                v0 += b0; v1 += b1; v2 += b0; v3 += b1;
                float* Cf = (float*)Cv;
                *reinterpret_cast<float2*>(&Cf[(size_t)row0 * N + col]) = make_float2(v0, v1);
                *reinterpret_cast<float2*>(&Cf[(size_t)(row0 + 8) * N + col]) = make_float2(v2, v3);
            }
        }
    }
}

// ---------------------------------------------------------------------------
// fp32 -> fp16 elementwise convert (grid-stride)
// ---------------------------------------------------------------------------
__global__ void f32_to_f16_kernel(const float4* __restrict__ in,
                                  uint2* __restrict__ outp, int n4)
{
    int i = blockIdx.x * blockDim.x + threadIdx.x;
    int stride = gridDim.x * blockDim.x;
    for (; i < n4; i += stride) {
        float4 v = in[i];
        __half2 a = __floats2half2_rn(v.x, v.y);
        __half2 b = __floats2half2_rn(v.z, v.w);
        uint2 o;
        o.x = *reinterpret_cast<uint32_t*>(&a);
        o.y = *reinterpret_cast<uint32_t*>(&b);
        outp[i] = o;
    }
}

// ---------------------------------------------------------------------------
// K2a: partial kv/ksum per (chunk, b, h); reads fp16 qkv
// ---------------------------------------------------------------------------
__global__ __launch_bounds__(256) void kv_partial_kernel()
{
    const int bh = blockIdx.x;
    const int chunk = blockIdx.y;
    const int b = bh >> 4, h = bh & 15;

    __shared__ float Ks[32][64];
    __shared__ float Vs[32][64];

    const int tid = threadIdx.x;
    const int tx = tid & 15, ty = tid >> 4;
    const int lr = tid >> 3;
    const int lc = (tid & 7) * 8;

    const __half* baseh = g_qkvh + (size_t)b * SEQ * QKV_COLS;
    const int k_col = DIM + h * HDIM;
    const int v_col = 2 * DIM + h * HDIM;

    float acc[4][4];
#pragma unroll
    for (int i = 0; i < 4; i++)
#pragma unroll
        for (int j = 0; j < 4; j++) acc[i][j] = 0.f;
    float ksum = 0.f;

    const int nbeg = chunk * CHUNK_ROWS;
    for (int n0 = nbeg; n0 < nbeg + CHUNK_ROWS; n0 += 32) {
        const __half* kp = baseh + (size_t)(n0 + lr) * QKV_COLS + k_col + lc;
        const __half* vp = baseh + (size_t)(n0 + lr) * QKV_COLS + v_col + lc;
        uint4 kr = *reinterpret_cast<const uint4*>(kp);   // 8 halves
        uint4 vr = *reinterpret_cast<const uint4*>(vp);
        const __half2* kh = reinterpret_cast<const __half2*>(&kr);
        const __half2* vh = reinterpret_cast<const __half2*>(&vr);
#pragma unroll
        for (int j = 0; j < 4; j++) {
            float2 kf = __half22float2(kh[j]);
            float2 vf = __half22float2(vh[j]);
            Ks[lr][lc + 2 * j]     = kf.x;
            Ks[lr][lc + 2 * j + 1] = kf.y;
            Vs[lr][lc + 2 * j]     = vf.x;
            Vs[lr][lc + 2 * j + 1] = vf.y;
        }
        __syncthreads();

#pragma unroll 8
        for (int kk = 0; kk < 32; kk++) {
            float rk[4], rv[4];
            *reinterpret_cast<float4*>(rk) = *reinterpret_cast<float4*>(&Ks[kk][ty * 4]);
            *reinterpret_cast<float4*>(rv) = *reinterpret_cast<float4*>(&Vs[kk][tx * 4]);
#pragma unroll
            for (int i = 0; i < 4; i++)
#pragma unroll
                for (int j = 0; j < 4; j++)
                    acc[i][j] = fmaf(rk[i], rv[j], acc[i][j]);
        }
        if (tid < 64) {
#pragma unroll
            for (int kk = 0; kk < 32; kk++) ksum += Ks[kk][tid];
        }
        __syncthreads();
    }

    float* kvout = g_kvp + ((size_t)chunk * 64 + bh) * HDIM * HDIM;
#pragma unroll
    for (int i = 0; i < 4; i++) {
        float4 v = make_float4(acc[i][0], acc[i][1], acc[i][2], acc[i][3]);
        *reinterpret_cast<float4*>(&kvout[(ty * 4 + i) * HDIM + tx * 4]) = v;
    }
    if (tid < 64) g_ksump[(chunk * 64 + bh) * HDIM + tid] = ksum;
}

// K2b: deterministic reduction over chunks
__global__ __launch_bounds__(256) void kv_reduce_kernel()
{
    const int bh = blockIdx.x;
    const int tid = threadIdx.x;
    for (int e = tid; e < HDIM * HDIM; e += 256) {
        float s = 0.f;
#pragma unroll
        for (int c = 0; c < NCHUNK; c++)
            s += g_kvp[((size_t)c * 64 + bh) * HDIM * HDIM + e];
        g_kv[(size_t)bh * HDIM * HDIM + e] = s;
    }
    if (tid < HDIM) {
        float s = 0.f;
#pragma unroll
        for (int c = 0; c < NCHUNK; c++)
            s += g_ksump[(c * 64 + bh) * HDIM + tid];
        g_ksum[bh * HDIM + tid] = s;
    }
}

// ---------------------------------------------------------------------------
// K3: out = (q @ kv) * z ; z = 1/(q . ksum + 1e-6); reads fp16 q, writes fp16
// ---------------------------------------------------------------------------
__global__ __launch_bounds__(256) void attn_out_kernel()
{
    const int bh = blockIdx.y;
    const int b = bh >> 4, h = bh & 15;
    const int n0 = blockIdx.x * 64;

    __shared__ float Qs[64][65];
    __shared__ float KVs[64 * 64];
    __shared__ float ksums[64];
    __shared__ float zsh[64];

    const int tid = threadIdx.x;

    const float* kvsrc = g_kv + (size_t)bh * HDIM * HDIM;
    for (int i = tid; i < (HDIM * HDIM) / 4; i += 256)
        reinterpret_cast<float4*>(KVs)[i] = reinterpret_cast<const float4*>(kvsrc)[i];
    if (tid < 64) ksums[tid] = g_ksum[bh * HDIM + tid];

    {
        const int qr = tid >> 2;
        const int qc = (tid & 3) * 16;
        const __half* qbase = g_qkvh + (size_t)(b * SEQ + n0 + qr) * QKV_COLS + h * HDIM + qc;
#pragma unroll
        for (int c = 0; c < 16; c += 8) {
            uint4 qr4 = *reinterpret_cast<const uint4*>(qbase + c);   // 8 halves
            const __half2* qh = reinterpret_cast<const __half2*>(&qr4);
#pragma unroll
            for (int j = 0; j < 4; j++) {
                float2 f = __half22float2(qh[j]);
                Qs[qr][qc + c + 2 * j]     = f.x;
                Qs[qr][qc + c + 2 * j + 1] = f.y;
            }
        }
    }
    __syncthreads();

    if (tid < 64) {
        float dot = 0.f;
#pragma unroll 8
        for (int d = 0; d < 64; d++) dot = fmaf(Qs[tid][d], ksums[d], dot);
        zsh[tid] = 1.f / (dot + 1e-6f);
    }
    __syncthreads();

    const int tx = tid & 15, ty = tid >> 4;
    const int r0 = ty * 4;
    const int e0 = tx * 4;

    float acc[4][4];
#pragma unroll
    for (int i = 0; i < 4; i++)
#pragma unroll
        for (int j = 0; j < 4; j++) acc[i][j] = 0.f;

#pragma unroll 4
    for (int d = 0; d < 64; d++) {
        float rb[4];
        *reinterpret_cast<float4*>(rb) = *reinterpret_cast<float4*>(&KVs[d * 64 + e0]);
        float ra0 = Qs[r0 + 0][d];
        float ra1 = Qs[r0 + 1][d];
        float ra2 = Qs[r0 + 2][d];
        float ra3 = Qs[r0 + 3][d];
#pragma unroll
        for (int j = 0; j < 4; j++) {
            acc[0][j] = fmaf(ra0, rb[j], acc[0][j]);
            acc[1][j] = fmaf(ra1, rb[j], acc[1][j]);
            acc[2][j] = fmaf(ra2, rb[j], acc[2][j]);
            acc[3][j] = fmaf(ra3, rb[j], acc[3][j]);
        }
    }

#pragma unroll
    for (int i = 0; i < 4; i++) {
        float z = zsh[r0 + i];
        __half2 h01 = __floats2half2_rn(acc[i][0] * z, acc[i][1] * z);
        __half2 h23 = __floats2half2_rn(acc[i][2] * z, acc[i][3] * z);
        uint2 o;
        o.x = *reinterpret_cast<uint32_t*>(&h01);
        o.y = *reinterpret_cast<uint32_t*>(&h23);
        size_t row = (size_t)(b * SEQ + n0 + r0 + i);
        *reinterpret_cast<uint2*>(&g_attnh[row * DIM + h * HDIM + e0]) = o;
    }
}

// ---------------------------------------------------------------------------
extern "C" void kernel_launch(void* const* d_in, const int* in_sizes, int n_in,
                              void* d_out, int out_size)
{
    const float* x      = (const float*)d_in[0];  // [4,4096,1024]
    const float* W_qkv  = (const float*)d_in[1];  // [1024,3072]
    const float* W_proj = (const float*)d_in[2];  // [1024,1024]
    const float* b_proj = (const float*)d_in[3];  // [1024]
    float* out = (float*)d_out;

    __half *qkvh_p, *xh_p, *attnh_p, *wqkvh_p, *wprojh_p;
    cudaGetSymbolAddress((void**)&qkvh_p, g_qkvh);
    cudaGetSymbolAddress((void**)&xh_p, g_xh);
    cudaGetSymbolAddress((void**)&attnh_p, g_attnh);
    cudaGetSymbolAddress((void**)&wqkvh_p, g_wqkvh);
    cudaGetSymbolAddress((void**)&wprojh_p, g_wprojh);

    cudaFuncSetAttribute(gemm_h<1>, cudaFuncAttributeMaxDynamicSharedMemorySize, SMEM_BYTES);
    cudaFuncSetAttribute(gemm_h<2>, cudaFuncAttributeMaxDynamicSharedMemorySize, SMEM_BYTES);

    // fp32 -> fp16 conversion passes
    f32_to_f16_kernel<<<2048, 256>>>((const float4*)x, (uint2*)xh_p,
                                     (int)((size_t)M_ROWS * DIM / 4));
    f32_to_f16_kernel<<<1024, 256>>>((const float4*)W_qkv, (uint2*)wqkvh_p,
                                     (int)((size_t)DIM * QKV_COLS / 4));
    f32_to_f16_kernel<<<512, 256>>>((const float4*)W_proj, (uint2*)wprojh_p,
                                    (int)((size_t)DIM * DIM / 4));

    // K1: qkv = x @ W_qkv (fp16 out), elu+1 fused on q/k columns
    gemm_h<1><<<dim3(QKV_COLS / 128, M_ROWS / 128), 256, SMEM_BYTES>>>(
        xh_p, wqkvh_p, qkvh_p, QKV_COLS, nullptr);

    // K2: kv state + ksum (chunked + deterministic reduce)
    kv_partial_kernel<<<dim3(BATCH * NHEAD, NCHUNK), 256>>>();
    kv_reduce_kernel<<<BATCH * NHEAD, 256>>>();

    // K3: normalized readout (fp16 in/out)
    attn_out_kernel<<<dim3(SEQ / 64, BATCH * NHEAD), 256>>>();

    // K4: out = attn @ W_proj + b_proj (fp32 out)
    gemm_h<2><<<dim3(DIM / 128, M_ROWS / 128), 256, SMEM_BYTES>>>(
        attnh_p, wprojh_p, out, DIM, b_proj);
}

// round 8
// speedup vs baseline: 2.4268x; 1.2812x over previous
#include <cuda_runtime.h>
#include <cuda_fp16.h>
#include <math.h>
#include <stdint.h>

// ---------------------------------------------------------------------------
// Problem constants
// ---------------------------------------------------------------------------
#define BATCH 4
#define SEQ 4096
#define DIM 1024
#define NHEAD 16
#define HDIM 64
#define M_ROWS (BATCH * SEQ)      // 16384
#define QKV_COLS (3 * DIM)        // 3072
#define NCHUNK 16
#define CHUNK_ROWS (SEQ / NCHUNK) // 256

// Scratch (device globals; allocation-free contract)
__device__ __half g_qkvh[(size_t)M_ROWS * QKV_COLS];
__device__ __half g_xh[(size_t)M_ROWS * DIM];
__device__ __half g_attnh[(size_t)M_ROWS * DIM];
__device__ __half g_wqkvh[(size_t)DIM * QKV_COLS];
__device__ __half g_wprojh[(size_t)DIM * DIM];
__device__ float  g_kvp[NCHUNK * 64 * HDIM * 72];     // fp32 partial kv_ext
__device__ __half g_kvh[64 * HDIM * 128];             // fp16 kv_ext [bh][64][128]

// ---------------------------------------------------------------------------
// Main GEMM geometry (unchanged from R7)
// ---------------------------------------------------------------------------
#define KT 64
#define NTILES (DIM / KT)
#define A_STAGE_BYTES (128 * 128)
#define B_STAGE_BYTES (64 * 256)
#define STAGE_BYTES (A_STAGE_BYTES + B_STAGE_BYTES)
#define GSTAGES 3
#define SMEM_BYTES (GSTAGES * STAGE_BYTES)

__device__ __forceinline__ uint32_t smem_u32(const void* p) {
    uint32_t a;
    asm("{ .reg .u64 t; cvta.to.shared.u64 t, %1; cvt.u32.u64 %0, t; }"
        : "=r"(a) : "l"(p));
    return a;
}
__device__ __forceinline__ void cp16(uint32_t dst, const void* src) {
    asm volatile("cp.async.cg.shared.global [%0], [%1], 16;" :: "r"(dst), "l"(src));
}
__device__ __forceinline__ void ldsm4(uint32_t& r0, uint32_t& r1, uint32_t& r2,
                                      uint32_t& r3, uint32_t a) {
    asm volatile("ldmatrix.sync.aligned.m8n8.x4.shared.b16 {%0,%1,%2,%3}, [%4];"
                 : "=r"(r0), "=r"(r1), "=r"(r2), "=r"(r3) : "r"(a));
}
__device__ __forceinline__ void ldsm4t(uint32_t& r0, uint32_t& r1, uint32_t& r2,
                                       uint32_t& r3, uint32_t a) {
    asm volatile("ldmatrix.sync.aligned.m8n8.x4.trans.shared.b16 {%0,%1,%2,%3}, [%4];"
                 : "=r"(r0), "=r"(r1), "=r"(r2), "=r"(r3) : "r"(a));
}
__device__ __forceinline__ void mma16816(float* c, const uint32_t* a, const uint32_t* b) {
    asm volatile(
        "mma.sync.aligned.m16n8k16.row.col.f32.f16.f16.f32 "
        "{%0,%1,%2,%3}, {%4,%5,%6,%7}, {%8,%9}, {%0,%1,%2,%3};"
        : "+f"(c[0]), "+f"(c[1]), "+f"(c[2]), "+f"(c[3])
        : "r"(a[0]), "r"(a[1]), "r"(a[2]), "r"(a[3]), "r"(b[0]), "r"(b[1]));
}

// ---------------------------------------------------------------------------
// Main fp16 GEMM (as R7): MODE 1 elu+1 -> half out; MODE 2 +bias -> float out
// ---------------------------------------------------------------------------
template <int MODE>
__global__ __launch_bounds__(256, 2) void gemm_h(
    const __half* __restrict__ Ah, const __half* __restrict__ Bh,
    void* __restrict__ Cv, int N, const float* __restrict__ bias)
{
    extern __shared__ char sm[];

    const int tid = threadIdx.x;
    const int bm = blockIdx.y * 128;
    const int bn = blockIdx.x * 128;
    const int lane = tid & 31, wid = tid >> 5;
    const int g = lane >> 2, tg = lane & 3;
    const int mw = (wid >> 1) * 32;
    const int nw = (wid & 1) * 64;
    const int l7 = lane & 7;
    const int grp = lane >> 3;

    float acc[2][8][4];
#pragma unroll
    for (int mi = 0; mi < 2; mi++)
#pragma unroll
        for (int ni = 0; ni < 8; ni++)
#pragma unroll
            for (int j = 0; j < 4; j++) acc[mi][ni][j] = 0.f;

    const uint32_t s0 = smem_u32(sm);

    uint32_t ldA_s[4], ldB_s[4];
#pragma unroll
    for (int i = 0; i < 4; i++) {
        int id = tid + i * 256;
        int row = id >> 3, c = id & 7;
        ldA_s[i] = row * 128 + ((c ^ (row & 7)) << 4);
        int rowb = id >> 4, cb = id & 15;
        ldB_s[i] = rowb * 256 + ((cb ^ (rowb & 7)) << 4);
    }

    auto load_tile = [&](int kt, int s) {
        const uint32_t sA = s0 + s * STAGE_BYTES;
        const uint32_t sB = sA + A_STAGE_BYTES;
#pragma unroll
        for (int i = 0; i < 4; i++) {
            int id = tid + i * 256;
            int row = id >> 3, c = id & 7;
            cp16(sA + ldA_s[i], Ah + (size_t)(bm + row) * DIM + kt * KT + c * 8);
        }
#pragma unroll
        for (int i = 0; i < 4; i++) {
            int id = tid + i * 256;
            int row = id >> 4, c = id & 15;
            cp16(sB + ldB_s[i], Bh + (size_t)(kt * KT + row) * N + bn + c * 8);
        }
        asm volatile("cp.async.commit_group;" ::: "memory");
    };

    uint32_t aBase[2];
#pragma unroll
    for (int mi = 0; mi < 2; mi++) {
        int row = mw + mi * 16 + l7 + (grp & 1) * 8;
        aBase[mi] = row * 128 + (((grp >> 1) ^ (row & 7)) << 4);
    }
    uint32_t bBase[4];
#pragma unroll
    for (int nj = 0; nj < 4; nj++) {
        int brow = l7 + (grp & 1) * 8;
        int c = (nw >> 3) + nj * 2 + (grp >> 1);
        bBase[nj] = brow * 256 + ((c ^ l7) << 4);
    }

    load_tile(0, 0);
    load_tile(1, 1);

    int s = 0;
    for (int kt = 0; kt < NTILES; ++kt) {
        if (kt < NTILES - 1) {
            asm volatile("cp.async.wait_group 1;" ::: "memory");
        } else {
            asm volatile("cp.async.wait_group 0;" ::: "memory");
        }
        __syncthreads();
        if (kt + 2 < NTILES) {
            int s2 = s + 2; if (s2 >= GSTAGES) s2 -= GSTAGES;
            load_tile(kt + 2, s2);
        }

        const uint32_t sA = s0 + s * STAGE_BYTES;
        const uint32_t sB = sA + A_STAGE_BYTES;

#pragma unroll
        for (int ks = 0; ks < 4; ks++) {
            uint32_t af[2][4];
#pragma unroll
            for (int mi = 0; mi < 2; mi++)
                ldsm4(af[mi][0], af[mi][1], af[mi][2], af[mi][3],
                      sA + (aBase[mi] ^ (ks << 5)));
            uint32_t bf[8][2];
#pragma unroll
            for (int nj = 0; nj < 4; nj++)
                ldsm4t(bf[2 * nj][0], bf[2 * nj][1], bf[2 * nj + 1][0], bf[2 * nj + 1][1],
                       sB + bBase[nj] + ks * 4096);
#pragma unroll
            for (int mi = 0; mi < 2; mi++)
#pragma unroll
                for (int ni = 0; ni < 8; ni++)
                    mma16816(acc[mi][ni], af[mi], bf[ni]);
        }
        if (++s >= GSTAGES) s = 0;
    }

#pragma unroll
    for (int mi = 0; mi < 2; mi++) {
#pragma unroll
        for (int ni = 0; ni < 8; ni++) {
            const int row0 = bm + mw + mi * 16 + g;
            const int col = bn + nw + ni * 8 + 2 * tg;
            float v0 = acc[mi][ni][0], v1 = acc[mi][ni][1];
            float v2 = acc[mi][ni][2], v3 = acc[mi][ni][3];
            if (MODE == 1) {
                if (col < 2048) {
                    v0 = (v0 > 0.f) ? (v0 + 1.f) : expf(v0);
                    v1 = (v1 > 0.f) ? (v1 + 1.f) : expf(v1);
                    v2 = (v2 > 0.f) ? (v2 + 1.f) : expf(v2);
                    v3 = (v3 > 0.f) ? (v3 + 1.f) : expf(v3);
                }
                __half* Ch = (__half*)Cv;
                *reinterpret_cast<__half2*>(&Ch[(size_t)row0 * N + col]) =
                    __floats2half2_rn(v0, v1);
                *reinterpret_cast<__half2*>(&Ch[(size_t)(row0 + 8) * N + col]) =
                    __floats2half2_rn(v2, v3);
            } else {
                float b0 = __ldg(&bias[col]), b1 = __ldg(&bias[col + 1]);
                v0 += b0; v1 += b1; v2 += b0; v3 += b1;
                float* Cf = (float*)Cv;
                *reinterpret_cast<float2*>(&Cf[(size_t)row0 * N + col]) = make_float2(v0, v1);
                *reinterpret_cast<float2*>(&Cf[(size_t)(row0 + 8) * N + col]) = make_float2(v2, v3);
            }
        }
    }
}

// ---------------------------------------------------------------------------
// Merged fp32 -> fp16 conversion (x, W_qkv, W_proj in one launch)
// ---------------------------------------------------------------------------
__global__ void convert_all_kernel(const float4* __restrict__ x, uint2* __restrict__ xh,
                                   const float4* __restrict__ wq, uint2* __restrict__ wqh,
                                   const float4* __restrict__ wp, uint2* __restrict__ wph)
{
    const int n1 = (int)((size_t)M_ROWS * DIM / 4);
    const int n2 = (int)((size_t)DIM * QKV_COLS / 4);
    const int n3 = (int)((size_t)DIM * DIM / 4);
    const int stride = gridDim.x * blockDim.x;
    int i0 = blockIdx.x * blockDim.x + threadIdx.x;
    for (int i = i0; i < n1; i += stride) {
        float4 v = x[i];
        __half2 a = __floats2half2_rn(v.x, v.y), b = __floats2half2_rn(v.z, v.w);
        uint2 o; o.x = *(uint32_t*)&a; o.y = *(uint32_t*)&b; xh[i] = o;
    }
    for (int i = i0; i < n2; i += stride) {
        float4 v = wq[i];
        __half2 a = __floats2half2_rn(v.x, v.y), b = __floats2half2_rn(v.z, v.w);
        uint2 o; o.x = *(uint32_t*)&a; o.y = *(uint32_t*)&b; wqh[i] = o;
    }
    for (int i = i0; i < n3; i += stride) {
        float4 v = wp[i];
        __half2 a = __floats2half2_rn(v.x, v.y), b = __floats2half2_rn(v.z, v.w);
        uint2 o; o.x = *(uint32_t*)&a; o.y = *(uint32_t*)&b; wph[i] = o;
    }
}

// ---------------------------------------------------------------------------
// K2a (tensor): per (bh, chunk): kv_ext[64 d][72] = sum_n k[n,d]*vext[n,e]
// where vext cols 0-63 = v, col 64 = 1.0 (gives ksum), cols 65-71 = 0.
// 4 warps, 128 thr; K-dim = 256 seq rows, staged 64 rows x 3 stages.
// ---------------------------------------------------------------------------
#define K2_K_STAGE_B (64 * 128)      // k tile: 64 n-rows x 128B
#define K2_V_STAGE_B (64 * 256)      // v tile: 64 n-rows x 256B (cols 64+ = ones/0)
#define K2_STAGE_B (K2_K_STAGE_B + K2_V_STAGE_B)
#define K2_SMEM (3 * K2_STAGE_B)     // 73728

__global__ __launch_bounds__(128) void kv_partial_tc()
{
    extern __shared__ char sm2[];
    const int bh = blockIdx.x;
    const int chunk = blockIdx.y;
    const int b = bh >> 4, h = bh & 15;

    const int tid = threadIdx.x;
    const int lane = tid & 31, wid = tid >> 5;
    const int g = lane >> 2, tg = lane & 3;
    const int l7 = lane & 7;
    const int grp = lane >> 3;
    const uint32_t s0 = smem_u32(sm2);

    // init ones-column chunk (chunk 8 of v tile) for all 3 stages
    for (int idx = tid; idx < 3 * 64; idx += 128) {
        int st = idx >> 6, r = idx & 63;
        uint32_t a = s0 + st * K2_STAGE_B + K2_K_STAGE_B + r * 256 + ((8 ^ (r & 7)) << 4);
        asm volatile("st.shared.v4.b32 [%0], {%1, %2, %3, %4};"
                     :: "r"(a), "r"(0x00003C00u), "r"(0u), "r"(0u), "r"(0u));  // {1.0h,0,...}
    }

    float acc[9][4];
#pragma unroll
    for (int nj = 0; nj < 9; nj++)
#pragma unroll
        for (int j = 0; j < 4; j++) acc[nj][j] = 0.f;

    const __half* baseh = g_qkvh + (size_t)b * SEQ * QKV_COLS;
    const int k_col = DIM + h * HDIM;
    const int v_col = 2 * DIM + h * HDIM;
    const int nbase = chunk * CHUNK_ROWS;

    auto load_tile = [&](int kt, int st) {
        const uint32_t sK = s0 + st * K2_STAGE_B;
        const uint32_t sV = sK + K2_K_STAGE_B;
        const int n0 = nbase + kt * 64;
#pragma unroll
        for (int i = 0; i < 4; i++) {
            int id = tid + i * 128;
            int row = id >> 3, c = id & 7;
            cp16(sK + row * 128 + ((c ^ (row & 7)) << 4),
                 baseh + (size_t)(n0 + row) * QKV_COLS + k_col + c * 8);
        }
#pragma unroll
        for (int i = 0; i < 4; i++) {
            int id = tid + i * 128;
            int row = id >> 3, c = id & 7;
            cp16(sV + row * 256 + ((c ^ (row & 7)) << 4),
                 baseh + (size_t)(n0 + row) * QKV_COLS + v_col + c * 8);
        }
        asm volatile("cp.async.commit_group;" ::: "memory");
    };

    // A (k, trans): row = ks*16 + l7 + (grp>>1)*8 ; chunk = wid*2 + (grp&1)
    const uint32_t aOff = (l7 + (grp >> 1) * 8) * 128 +
                          (((wid * 2 + (grp & 1)) ^ l7) << 4);
    // B (vext, trans): row = ks*16 + l7 + (grp&1)*8 ; chunk = nj*2 + (grp>>1)
    uint32_t bOff[5];
#pragma unroll
    for (int p = 0; p < 5; p++)
        bOff[p] = (l7 + (grp & 1) * 8) * 256 + (((p * 2 + (grp >> 1)) ^ l7) << 4);

    load_tile(0, 0);
    load_tile(1, 1);

    int st = 0;
    for (int kt = 0; kt < 4; ++kt) {
        if (kt < 3) {
            asm volatile("cp.async.wait_group 1;" ::: "memory");
        } else {
            asm volatile("cp.async.wait_group 0;" ::: "memory");
        }
        __syncthreads();
        if (kt + 2 < 4) {
            int s2 = st + 2; if (s2 >= 3) s2 -= 3;
            load_tile(kt + 2, s2);
        }

        const uint32_t sK = s0 + st * K2_STAGE_B;
        const uint32_t sV = sK + K2_K_STAGE_B;

#pragma unroll
        for (int ks = 0; ks < 4; ks++) {
            uint32_t af[4];
            ldsm4t(af[0], af[1], af[2], af[3], sK + aOff + ks * 2048);
            uint32_t bf[10][2];
#pragma unroll
            for (int p = 0; p < 5; p++)
                ldsm4t(bf[2 * p][0], bf[2 * p][1], bf[2 * p + 1][0], bf[2 * p + 1][1],
                       sV + bOff[p] + ks * 4096);
#pragma unroll
            for (int nj = 0; nj < 9; nj++)
                mma16816(acc[nj], af, bf[nj]);
        }
        if (++st >= 3) st = 0;
    }

    // store fp32 partials: [chunk][bh][64 d][72]
    float* outp = g_kvp + ((size_t)chunk * 64 + bh) * (HDIM * 72);
#pragma unroll
    for (int nj = 0; nj < 9; nj++) {
        int d0 = wid * 16 + g;
        int e = nj * 8 + 2 * tg;
        *reinterpret_cast<float2*>(&outp[d0 * 72 + e]) = make_float2(acc[nj][0], acc[nj][1]);
        *reinterpret_cast<float2*>(&outp[(d0 + 8) * 72 + e]) = make_float2(acc[nj][2], acc[nj][3]);
    }
}

// K2b: deterministic reduce over chunks -> fp16 kv_ext [bh][64][128]
__global__ __launch_bounds__(256) void kv_reduce_kernel()
{
    const int bh = blockIdx.x;
    const int tid = threadIdx.x;
    for (int idx = tid; idx < HDIM * 72; idx += 256) {
        int d = idx / 72, e = idx % 72;
        float s = 0.f;
#pragma unroll
        for (int c = 0; c < NCHUNK; c++)
            s += g_kvp[((size_t)c * 64 + bh) * (HDIM * 72) + idx];
        g_kvh[(size_t)bh * HDIM * 128 + d * 128 + e] = __float2half_rn(s);
    }
    // zero the unread tail of chunk-8 region is covered (e=65..71 sums of zeros)
    for (int idx = tid; idx < HDIM * 56; idx += 256) {   // cols 72-127 -> zero (safety)
        int d = idx / 56, e = 72 + idx % 56;
        g_kvh[(size_t)bh * HDIM * 128 + d * 128 + e] = __float2half_rn(0.f);
    }
}

// ---------------------------------------------------------------------------
// K3 (tensor): per (bh, 64-row tile): O = Q[64x64] @ KV_ext[64x72];
// col 64 = q.ksum -> z = 1/(col64 + 1e-6); store fp16 attn = O[:,0:64]*z
// ---------------------------------------------------------------------------
__global__ __launch_bounds__(128) void attn_out_tc()
{
    __shared__ __align__(16) char qbuf[64 * 128];    // q tile 64 x 64 halves
    __shared__ __align__(16) char kvbuf[64 * 256];   // kv tile 64 x 128 halves

    const int bh = blockIdx.y;
    const int b = bh >> 4, h = bh & 15;
    const int n0 = blockIdx.x * 64;

    const int tid = threadIdx.x;
    const int lane = tid & 31, wid = tid >> 5;
    const int g = lane >> 2, tg = lane & 3;
    const int l7 = lane & 7;
    const int grp = lane >> 3;

    const uint32_t sQ = smem_u32(qbuf);
    const uint32_t sKV = smem_u32(kvbuf);

    // load q tile: 64 rows x 8 chunks
    const __half* qsrc = g_qkvh + (size_t)(b * SEQ + n0) * QKV_COLS + h * HDIM;
#pragma unroll
    for (int i = 0; i < 4; i++) {
        int id = tid + i * 128;
        int row = id >> 3, c = id & 7;
        cp16(sQ + row * 128 + ((c ^ (row & 7)) << 4),
             qsrc + (size_t)row * QKV_COLS + c * 8);
    }
    // load kv tile: 64 rows x 16 chunks
    const __half* kvsrc = g_kvh + (size_t)bh * HDIM * 128;
#pragma unroll
    for (int i = 0; i < 8; i++) {
        int id = tid + i * 128;
        int row = id >> 4, c = id & 15;
        cp16(sKV + row * 256 + ((c ^ (row & 7)) << 4), kvsrc + row * 128 + c * 8);
    }
    asm volatile("cp.async.commit_group;" ::: "memory");
    asm volatile("cp.async.wait_group 0;" ::: "memory");
    __syncthreads();

    float acc[9][4];
#pragma unroll
    for (int nj = 0; nj < 9; nj++)
#pragma unroll
        for (int j = 0; j < 4; j++) acc[nj][j] = 0.f;

    // A (q, row-major): row = wid*16 + l7 + (grp&1)*8, chunk base grp>>1
    const int arow = wid * 16 + l7 + (grp & 1) * 8;
    const uint32_t aBase = arow * 128 + (((grp >> 1) ^ (arow & 7)) << 4);
    // B (kv, [K][N] trans)
    uint32_t bOff[5];
#pragma unroll
    for (int p = 0; p < 5; p++)
        bOff[p] = (l7 + (grp & 1) * 8) * 256 + (((p * 2 + (grp >> 1)) ^ l7) << 4);

#pragma unroll
    for (int ks = 0; ks < 4; ks++) {
        uint32_t af[4];
        ldsm4(af[0], af[1], af[2], af[3], sQ + (aBase ^ (ks << 5)));
        uint32_t bf[10][2];
#pragma unroll
        for (int p = 0; p < 5; p++)
            ldsm4t(bf[2 * p][0], bf[2 * p][1], bf[2 * p + 1][0], bf[2 * p + 1][1],
                   sKV + bOff[p] + ks * 4096);
#pragma unroll
        for (int nj = 0; nj < 9; nj++)
            mma16816(acc[nj], af, bf[nj]);
    }

    // z from column 64 (held at tg==0 in acc[8][0] / acc[8][2])
    float dlo = __shfl_sync(0xffffffffu, acc[8][0], lane & 28);
    float dhi = __shfl_sync(0xffffffffu, acc[8][2], lane & 28);
    float zlo = 1.f / (dlo + 1e-6f);
    float zhi = 1.f / (dhi + 1e-6f);

    __half* outp = g_attnh + (size_t)(b * SEQ + n0) * DIM + h * HDIM;
#pragma unroll
    for (int nj = 0; nj < 8; nj++) {
        int r = wid * 16 + g;
        int e = nj * 8 + 2 * tg;
        *reinterpret_cast<__half2*>(&outp[(size_t)r * DIM + e]) =
            __floats2half2_rn(acc[nj][0] * zlo, acc[nj][1] * zlo);
        *reinterpret_cast<__half2*>(&outp[(size_t)(r + 8) * DIM + e]) =
            __floats2half2_rn(acc[nj][2] * zhi, acc[nj][3] * zhi);
    }
}

// ---------------------------------------------------------------------------
extern "C" void kernel_launch(void* const* d_in, const int* in_sizes, int n_in,
                              void* d_out, int out_size)
{
    const float* x      = (const float*)d_in[0];
    const float* W_qkv  = (const float*)d_in[1];
    const float* W_proj = (const float*)d_in[2];
    const float* b_proj = (const float*)d_in[3];
    float* out = (float*)d_out;

    __half *qkvh_p, *xh_p, *attnh_p, *wqkvh_p, *wprojh_p;
    cudaGetSymbolAddress((void**)&qkvh_p, g_qkvh);
    cudaGetSymbolAddress((void**)&xh_p, g_xh);
    cudaGetSymbolAddress((void**)&attnh_p, g_attnh);
    cudaGetSymbolAddress((void**)&wqkvh_p, g_wqkvh);
    cudaGetSymbolAddress((void**)&wprojh_p, g_wprojh);

    cudaFuncSetAttribute(gemm_h<1>, cudaFuncAttributeMaxDynamicSharedMemorySize, SMEM_BYTES);
    cudaFuncSetAttribute(gemm_h<2>, cudaFuncAttributeMaxDynamicSharedMemorySize, SMEM_BYTES);
    cudaFuncSetAttribute(kv_partial_tc, cudaFuncAttributeMaxDynamicSharedMemorySize, K2_SMEM);

    // merged fp32 -> fp16 conversions
    convert_all_kernel<<<2048, 256>>>((const float4*)x, (uint2*)xh_p,
                                      (const float4*)W_qkv, (uint2*)wqkvh_p,
                                      (const float4*)W_proj, (uint2*)wprojh_p);

    // K1: qkv = x @ W_qkv (fp16 out), elu+1 fused on q/k columns
    gemm_h<1><<<dim3(QKV_COLS / 128, M_ROWS / 128), 256, SMEM_BYTES>>>(
        xh_p, wqkvh_p, qkvh_p, QKV_COLS, nullptr);

    // K2: kv_ext partials (tensor cores, ones-column ksum) + reduce
    kv_partial_tc<<<dim3(64, NCHUNK), 128, K2_SMEM>>>();
    kv_reduce_kernel<<<64, 256>>>();

    // K3: normalized readout (tensor cores, fused z via column 64)
    attn_out_tc<<<dim3(SEQ / 64, 64), 128>>>();

    // K4: out = attn @ W_proj + b_proj (fp32 out)
    gemm_h<2><<<dim3(DIM / 128, M_ROWS / 128), 256, SMEM_BYTES>>>(
        attnh_p, wprojh_p, out, DIM, b_proj);
}